// round 15
// baseline (speedup 1.0000x reference)
#include <cuda_runtime.h>
#include <cuda_bf16.h>
#include <cstdint>

// ---------------- problem constants ----------------
#define K_TOTAL 33154
#define SEG1    16641
#define SEG2    16770
#define AT_LEN  129
#define ST1_LEN 16384
#define NBATCH  1024
#define NHID    512
#define NOUT    129

// ---------------- padded / tiling constants ----------------
#define SPLITK  9
#define CK      64
#define NCHUNK  58
#define KSPLIT  (NCHUNK * CK)        // 3712
#define KPAD    (SPLITK * KSPLIT)    // 33408
#define TM      128
#define TN      256
#define MT      (NBATCH / TM)        // 8
#define NT      (NHID  / TN)         // 2  -> grid 8*2*9 = 144 CTAs (one wave)
#define GTHREADS 512                 // 16 warps: 2(M) x 8(N), warp tile 64x32

// ---------------- device scratch ----------------
__device__ float g_hpart[SPLITK][NBATCH][NHID];                 // 18 MB
__device__ __align__(128) __nv_bfloat16 g_xh[NBATCH][KPAD];
__device__ __align__(128) __nv_bfloat16 g_xl[NBATCH][KPAD];
__device__ __align__(128) __nv_bfloat16 g_wh[NHID][KPAD];
__device__ __align__(128) __nv_bfloat16 g_wl[NHID][KPAD];

// ---------------- helpers ----------------
__device__ __forceinline__ uint32_t smem_u32(const void* p) {
    uint32_t a;
    asm("{ .reg .u64 t; cvta.to.shared.u64 t, %1; cvt.u32.u64 %0, t; }"
        : "=r"(a) : "l"(p));
    return a;
}
#define SWZ128(o) (((uint32_t)(o)) ^ ((((uint32_t)(o)) >> 3) & 0x70u))

__device__ __forceinline__ void cp_async16(uint32_t dst, const void* src) {
    asm volatile("cp.async.cg.shared.global [%0], [%1], 16;" :: "r"(dst), "l"(src) : "memory");
}
#define CP_COMMIT() asm volatile("cp.async.commit_group;" ::: "memory")
#define CP_WAIT1()  asm volatile("cp.async.wait_group 1;" ::: "memory")
#define CP_WAIT0()  asm volatile("cp.async.wait_group 0;" ::: "memory")

#define LDM_X4(r0, r1, r2, r3, a) \
    asm volatile("ldmatrix.sync.aligned.m8n8.x4.shared.b16 {%0,%1,%2,%3}, [%4];" \
                 : "=r"(r0), "=r"(r1), "=r"(r2), "=r"(r3) : "r"(a))

__device__ __forceinline__ void mma_bf16(float* c, const uint32_t* a, const uint32_t* b) {
    asm volatile(
        "mma.sync.aligned.m16n8k16.row.col.f32.bf16.bf16.f32 "
        "{%0,%1,%2,%3}, {%4,%5,%6,%7}, {%8,%9}, {%0,%1,%2,%3};"
        : "+f"(c[0]), "+f"(c[1]), "+f"(c[2]), "+f"(c[3])
        : "r"(a[0]), "r"(a[1]), "r"(a[2]), "r"(a[3]), "r"(b[0]), "r"(b[1]));
}

// ---------------- x concat access ----------------
__device__ __forceinline__ float load_x(const float* __restrict__ st,
                                        const float* __restrict__ at,
                                        const float* __restrict__ st1,
                                        int b, int k) {
    if (k < SEG1)  return st [b * SEG1    + k];
    if (k < SEG2)  return at [b * AT_LEN  + (k - SEG1)];
    return st1[b * ST1_LEN + (k - SEG2)];
}

// ======================================================================
// Merged convert kernel (verified 68.6us @ ~5.9TB/s effective):
//   blocks [0, XBLOCKS)              : convert_x (8 fp32/thread -> STG.128)
//   blocks [XBLOCKS, XBLOCKS+WBLOCKS): convert_w (32x32 transpose tiles)
// ======================================================================
#define XBLK_PER_ROW ((KPAD + 2047) / 2048)      // 17
#define XBLOCKS (XBLK_PER_ROW * NBATCH)          // 17408
#define WBLK_K  (KPAD / 32)                      // 1044
#define WBLK_N  (NHID / 32)                      // 16
#define WBLOCKS (WBLK_K * WBLK_N)                // 16704

__global__ void __launch_bounds__(256)
convert_all_kernel(const float* __restrict__ st, const float* __restrict__ at,
                   const float* __restrict__ st1, const float* __restrict__ W1)
{
    if (blockIdx.x < XBLOCKS) {
        const int m  = blockIdx.x / XBLK_PER_ROW;
        const int bx = blockIdx.x - m * XBLK_PER_ROW;
        const int k  = (bx * 256 + threadIdx.x) * 8;
        if (k >= KPAD) return;
        float v[8];
        #pragma unroll
        for (int i = 0; i < 8; i++)
            v[i] = (k + i < K_TOTAL) ? load_x(st, at, st1, m, k + i) : 0.0f;

        uint32_t hp[4], lp[4];
        #pragma unroll
        for (int i = 0; i < 4; i++) {
            __nv_bfloat16 h0 = __float2bfloat16(v[2*i]);
            __nv_bfloat16 h1 = __float2bfloat16(v[2*i+1]);
            __nv_bfloat16 l0 = __float2bfloat16(v[2*i]   - __bfloat162float(h0));
            __nv_bfloat16 l1 = __float2bfloat16(v[2*i+1] - __bfloat162float(h1));
            __nv_bfloat162 hh(h0, h1), ll(l0, l1);
            hp[i] = *reinterpret_cast<uint32_t*>(&hh);
            lp[i] = *reinterpret_cast<uint32_t*>(&ll);
        }
        *reinterpret_cast<uint4*>(&g_xh[m][k]) = make_uint4(hp[0], hp[1], hp[2], hp[3]);
        *reinterpret_cast<uint4*>(&g_xl[m][k]) = make_uint4(lp[0], lp[1], lp[2], lp[3]);
    } else {
        __shared__ float tile[32][33];
        const int widx = blockIdx.x - XBLOCKS;
        const int bk = widx / WBLK_N;
        const int bn = widx - bk * WBLK_N;
        const int k0 = bk * 32;
        const int n0 = bn * 32;
        const int tx = threadIdx.x & 31;
        const int ty = threadIdx.x >> 5;

        #pragma unroll
        for (int i = 0; i < 4; i++) {
            int k = k0 + ty + i * 8;
            tile[ty + i * 8][tx] = (k < K_TOTAL) ? W1[(size_t)k * NHID + n0 + tx] : 0.0f;
        }
        __syncthreads();
        #pragma unroll
        for (int i = 0; i < 4; i++) {
            int n = n0 + ty + i * 8;
            float v = tile[tx][ty + i * 8];
            __nv_bfloat16 h = __float2bfloat16(v);
            __nv_bfloat16 l = __float2bfloat16(v - __bfloat162float(h));
            g_wh[n][k0 + tx] = h;
            g_wl[n][k0 + tx] = l;
        }
    }
}

// ======================================================================
// GEMM1: CTA tile 128(M) x 256(N), split-K over z, chunks of K=64,
// double-buffered 192KB smem. NOW 512 threads = 16 warps as 2(M) x 8(N),
// warp tile 64x32 -> 4 warps/SMSP to hide ldsm/sync latency.
// 3 bf16 passes (xh*wh + xh*wl + xl*wh) accumulated in fp32.
// ======================================================================
__global__ void __launch_bounds__(GTHREADS, 1)
gemm_mma_kernel()
{
    extern __shared__ char dyn_smem[];
    const uint32_t base = (smem_u32(dyn_smem) + 1023u) & ~1023u;

    const int tid  = threadIdx.x;
    const int wid  = tid >> 5;
    const int lane = tid & 31;

    const int m0 = blockIdx.x * TM;
    const int n0 = blockIdx.y * TN;
    const int split = blockIdx.z;
    const int kbase = split * KSPLIT;

    const int mwarp = (wid >> 3) * 64;   // 0 or 64
    const int nwarp = (wid & 7) * 32;    // 0,32,...,224

    const int a_row = lane & 15;
    const int a_col = (lane >> 4) * 16;
    const int b_row = (lane & 7) + ((lane >> 4) << 3);
    const int b_col = ((lane >> 3) & 1) * 16;

    float c[4][4][4];
    #pragma unroll
    for (int i = 0; i < 4; i++)
        #pragma unroll
        for (int j = 0; j < 4; j++)
            #pragma unroll
            for (int e = 0; e < 4; e++) c[i][j][e] = 0.0f;

    const uint32_t BUFSZ = 98304u;   // 96 KB

    auto issue_loads = [&](int ch) {
        const int k0 = kbase + ch * CK;
        const uint32_t buf = base + ((ch & 1) ? BUFSZ : 0u);
        const __nv_bfloat16* axh = &g_xh[m0][k0];
        const __nv_bfloat16* axl = &g_xl[m0][k0];
        // A tiles: 128 rows x 8 quads = 1024 quads each -> 2 per thread
        #pragma unroll
        for (int t = 0; t < 2; t++) {
            int q = tid + t * GTHREADS;
            int row = q >> 3, qc = q & 7;
            uint32_t off = SWZ128(row * 128 + qc * 16);
            cp_async16(buf +            off, axh + (size_t)row * KPAD + qc * 8);
            cp_async16(buf + 16384u +   off, axl + (size_t)row * KPAD + qc * 8);
        }
        const __nv_bfloat16* bwh = &g_wh[n0][k0];
        const __nv_bfloat16* bwl = &g_wl[n0][k0];
        // B tiles: 256 rows x 8 quads = 2048 quads each -> 4 per thread
        #pragma unroll
        for (int t = 0; t < 4; t++) {
            int q = tid + t * GTHREADS;
            int row = q >> 3, qc = q & 7;
            uint32_t off = SWZ128(row * 128 + qc * 16);
            cp_async16(buf + 32768u + off, bwh + (size_t)row * KPAD + qc * 8);
            cp_async16(buf + 65536u + off, bwl + (size_t)row * KPAD + qc * 8);
        }
        CP_COMMIT();
    };

    issue_loads(0);

    for (int i = 0; i < NCHUNK; i++) {
        if (i + 1 < NCHUNK) { issue_loads(i + 1); CP_WAIT1(); }
        else                { CP_WAIT0(); }
        __syncthreads();

        const uint32_t buf = base + ((i & 1) ? BUFSZ : 0u);
        const uint32_t Ah = buf, Al = buf + 16384u;
        const uint32_t Bh = buf + 32768u, Bl = buf + 65536u;

        #pragma unroll
        for (int kk = 0; kk < 4; kk++) {
            uint32_t ah[4][4], al[4][4];
            #pragma unroll
            for (int t = 0; t < 4; t++) {
                uint32_t offA = SWZ128((mwarp + t * 16 + a_row) * 128 + kk * 32 + a_col);
                LDM_X4(ah[t][0], ah[t][1], ah[t][2], ah[t][3], Ah + offA);
                LDM_X4(al[t][0], al[t][1], al[t][2], al[t][3], Al + offA);
            }
            uint32_t bh[4][2], bl[4][2];
            #pragma unroll
            for (int t = 0; t < 2; t++) {
                uint32_t offB = SWZ128((nwarp + t * 16 + b_row) * 128 + kk * 32 + b_col);
                LDM_X4(bh[2*t][0], bh[2*t][1], bh[2*t+1][0], bh[2*t+1][1], Bh + offB);
                LDM_X4(bl[2*t][0], bl[2*t][1], bl[2*t+1][0], bl[2*t+1][1], Bl + offB);
            }
            #pragma unroll
            for (int mi = 0; mi < 4; mi++)
                #pragma unroll
                for (int nj = 0; nj < 4; nj++) {
                    float* acc = c[mi][nj];
                    mma_bf16(acc, ah[mi], bh[nj]);   // xh * wh
                    mma_bf16(acc, ah[mi], bl[nj]);   // xh * wl
                    mma_bf16(acc, al[mi], bh[nj]);   // xl * wh
                }
        }
        __syncthreads();
    }

    // epilogue: m16n8 frag -> rows (lane/4, +8), cols 2*(lane%4)
    const int er = lane >> 2;
    const int ec = (lane & 3) * 2;
    #pragma unroll
    for (int mi = 0; mi < 4; mi++) {
        const int row = m0 + mwarp + mi * 16 + er;
        #pragma unroll
        for (int nj = 0; nj < 4; nj++) {
            const int col = n0 + nwarp + nj * 8 + ec;
            *reinterpret_cast<float2*>(&g_hpart[split][row][col]) =
                make_float2(c[mi][nj][0], c[mi][nj][1]);
            *reinterpret_cast<float2*>(&g_hpart[split][row + 8][col]) =
                make_float2(c[mi][nj][2], c[mi][nj][3]);
        }
    }
}

// ======================================================================
// Stage 2 (verified 26us shape): one CTA per batch row.
// Reduce split-K partials, +b1, ReLU, then h @ W2 + b2.
// ======================================================================
__global__ void __launch_bounds__(256)
mlp2_kernel(const float* __restrict__ b1,
            const float* __restrict__ W2,
            const float* __restrict__ b2,
            float* __restrict__ out)
{
    __shared__ float hs[NHID];
    const int b   = blockIdx.x;
    const int tid = threadIdx.x;

    #pragma unroll
    for (int n = tid; n < NHID; n += 256) {
        float s = 0.0f;
        #pragma unroll
        for (int sp = 0; sp < SPLITK; sp++) s += g_hpart[sp][b][n];
        s += b1[n];
        hs[n] = fmaxf(s, 0.0f);
    }
    __syncthreads();

    if (tid < NOUT) {
        float a0 = 0.f, a1 = 0.f, a2 = 0.f, a3 = 0.f;
        #pragma unroll 8
        for (int n = 0; n < NHID; n += 4) {
            a0 = fmaf(hs[n + 0], W2[(n + 0) * NOUT + tid], a0);
            a1 = fmaf(hs[n + 1], W2[(n + 1) * NOUT + tid], a1);
            a2 = fmaf(hs[n + 2], W2[(n + 2) * NOUT + tid], a2);
            a3 = fmaf(hs[n + 3], W2[(n + 3) * NOUT + tid], a3);
        }
        out[b * NOUT + tid] = (a0 + a1) + (a2 + a3) + b2[tid];
    }
}

// ======================================================================
// kernel_launch — graph-capturable, allocation-free.
// Input order (metadata): st, at, st1, W1, b1, W2, b2. Output: float32.
// ======================================================================
extern "C" void kernel_launch(void* const* d_in, const int* in_sizes, int n_in,
                              void* d_out, int out_size)
{
    const float* st  = (const float*)d_in[0];
    const float* at  = (const float*)d_in[1];
    const float* st1 = (const float*)d_in[2];
    const float* W1  = (const float*)d_in[3];
    const float* b1  = (const float*)d_in[4];
    const float* W2  = (const float*)d_in[5];
    const float* b2  = (const float*)d_in[6];
    float* out = (float*)d_out;

    convert_all_kernel<<<XBLOCKS + WBLOCKS, 256>>>(st, at, st1, W1);

    const int dyn_smem = 2 * 98304 + 1024;   // 192 KB + align slack
    cudaFuncSetAttribute(gemm_mma_kernel,
                         cudaFuncAttributeMaxDynamicSharedMemorySize, dyn_smem);
    dim3 gg(MT, NT, SPLITK);                 // 8 x 2 x 9 = 144 CTAs, one wave
    gemm_mma_kernel<<<gg, GTHREADS, dyn_smem>>>();

    mlp2_kernel<<<NBATCH, 256>>>(b1, W2, b2, out);
}

// round 16
// speedup vs baseline: 1.0930x; 1.0930x over previous
#include <cuda_runtime.h>
#include <cuda_bf16.h>
#include <cstdint>

// ---------------- problem constants ----------------
#define K_TOTAL 33154
#define SEG1    16641
#define SEG2    16770
#define AT_LEN  129
#define ST1_LEN 16384
#define NBATCH  1024
#define NHID    512
#define NOUT    129

// ---------------- padded / tiling constants ----------------
#define SPLITK  9
#define CK      64
#define NCHUNK  58
#define KSPLIT  (NCHUNK * CK)        // 3712
#define KPAD    (SPLITK * KSPLIT)    // 33408
#define TM      128
#define TN      256
#define MT      (NBATCH / TM)        // 8
#define NT      (NHID  / TN)         // 2  -> grid 8*2*9 = 144 CTAs (one wave)

// ---------------- device scratch ----------------
__device__ float g_hpart[SPLITK][NBATCH][NHID];                 // 18 MB
__device__ __align__(128) __nv_bfloat16 g_xh[NBATCH][KPAD];
__device__ __align__(128) __nv_bfloat16 g_xl[NBATCH][KPAD];
__device__ __align__(128) __nv_bfloat16 g_wh[NHID][KPAD];
__device__ __align__(128) __nv_bfloat16 g_wl[NHID][KPAD];

// ---------------- helpers ----------------
__device__ __forceinline__ uint32_t smem_u32(const void* p) {
    uint32_t a;
    asm("{ .reg .u64 t; cvta.to.shared.u64 t, %1; cvt.u32.u64 %0, t; }"
        : "=r"(a) : "l"(p));
    return a;
}
#define SWZ128(o) (((uint32_t)(o)) ^ ((((uint32_t)(o)) >> 3) & 0x70u))

__device__ __forceinline__ void cp_async16(uint32_t dst, const void* src) {
    asm volatile("cp.async.cg.shared.global [%0], [%1], 16;" :: "r"(dst), "l"(src) : "memory");
}
#define CP_COMMIT() asm volatile("cp.async.commit_group;" ::: "memory")
#define CP_WAIT0()  asm volatile("cp.async.wait_group 0;" ::: "memory")

#define LDM_X4(r0, r1, r2, r3, a) \
    asm volatile("ldmatrix.sync.aligned.m8n8.x4.shared.b16 {%0,%1,%2,%3}, [%4];" \
                 : "=r"(r0), "=r"(r1), "=r"(r2), "=r"(r3) : "r"(a))

__device__ __forceinline__ void mma_bf16(float* c, const uint32_t* a, const uint32_t* b) {
    asm volatile(
        "mma.sync.aligned.m16n8k16.row.col.f32.bf16.bf16.f32 "
        "{%0,%1,%2,%3}, {%4,%5,%6,%7}, {%8,%9}, {%0,%1,%2,%3};"
        : "+f"(c[0]), "+f"(c[1]), "+f"(c[2]), "+f"(c[3])
        : "r"(a[0]), "r"(a[1]), "r"(a[2]), "r"(a[3]), "r"(b[0]), "r"(b[1]));
}

// ---------------- x concat access ----------------
__device__ __forceinline__ float load_x(const float* __restrict__ st,
                                        const float* __restrict__ at,
                                        const float* __restrict__ st1,
                                        int b, int k) {
    if (k < SEG1)  return st [b * SEG1    + k];
    if (k < SEG2)  return at [b * AT_LEN  + (k - SEG1)];
    return st1[b * ST1_LEN + (k - SEG2)];
}

// ======================================================================
// Merged convert kernel (verified 68.6us @ ~5.9TB/s effective):
//   blocks [0, XBLOCKS)              : convert_x (8 fp32/thread -> STG.128)
//   blocks [XBLOCKS, XBLOCKS+WBLOCKS): convert_w (32x32 transpose tiles)
// ======================================================================
#define XBLK_PER_ROW ((KPAD + 2047) / 2048)      // 17
#define XBLOCKS (XBLK_PER_ROW * NBATCH)          // 17408
#define WBLK_K  (KPAD / 32)                      // 1044
#define WBLK_N  (NHID / 32)                      // 16
#define WBLOCKS (WBLK_K * WBLK_N)                // 16704

__global__ void __launch_bounds__(256)
convert_all_kernel(const float* __restrict__ st, const float* __restrict__ at,
                   const float* __restrict__ st1, const float* __restrict__ W1)
{
    if (blockIdx.x < XBLOCKS) {
        const int m  = blockIdx.x / XBLK_PER_ROW;
        const int bx = blockIdx.x - m * XBLK_PER_ROW;
        const int k  = (bx * 256 + threadIdx.x) * 8;
        if (k >= KPAD) return;
        float v[8];
        #pragma unroll
        for (int i = 0; i < 8; i++)
            v[i] = (k + i < K_TOTAL) ? load_x(st, at, st1, m, k + i) : 0.0f;

        uint32_t hp[4], lp[4];
        #pragma unroll
        for (int i = 0; i < 4; i++) {
            __nv_bfloat16 h0 = __float2bfloat16(v[2*i]);
            __nv_bfloat16 h1 = __float2bfloat16(v[2*i+1]);
            __nv_bfloat16 l0 = __float2bfloat16(v[2*i]   - __bfloat162float(h0));
            __nv_bfloat16 l1 = __float2bfloat16(v[2*i+1] - __bfloat162float(h1));
            __nv_bfloat162 hh(h0, h1), ll(l0, l1);
            hp[i] = *reinterpret_cast<uint32_t*>(&hh);
            lp[i] = *reinterpret_cast<uint32_t*>(&ll);
        }
        *reinterpret_cast<uint4*>(&g_xh[m][k]) = make_uint4(hp[0], hp[1], hp[2], hp[3]);
        *reinterpret_cast<uint4*>(&g_xl[m][k]) = make_uint4(lp[0], lp[1], lp[2], lp[3]);
    } else {
        __shared__ float tile[32][33];
        const int widx = blockIdx.x - XBLOCKS;
        const int bk = widx / WBLK_N;
        const int bn = widx - bk * WBLK_N;
        const int k0 = bk * 32;
        const int n0 = bn * 32;
        const int tx = threadIdx.x & 31;
        const int ty = threadIdx.x >> 5;

        #pragma unroll
        for (int i = 0; i < 4; i++) {
            int k = k0 + ty + i * 8;
            tile[ty + i * 8][tx] = (k < K_TOTAL) ? W1[(size_t)k * NHID + n0 + tx] : 0.0f;
        }
        __syncthreads();
        #pragma unroll
        for (int i = 0; i < 4; i++) {
            int n = n0 + ty + i * 8;
            float v = tile[tx][ty + i * 8];
            __nv_bfloat16 h = __float2bfloat16(v);
            __nv_bfloat16 l = __float2bfloat16(v - __bfloat162float(h));
            g_wh[n][k0 + tx] = h;
            g_wl[n][k0 + tx] = l;
        }
    }
}

// ======================================================================
// GEMM1 (R14 shape, restructured loop): CTA tile 128(M) x 256(N),
// split-K over z, chunks of K=64, double-buffered 192KB smem. 256
// threads = 8 warps as 2(M) x 4(N), warp tile 64x64. Per chunk: ONE
// __syncthreads; next-chunk cp.async issue happens after kk=0 so the
// LSU issue cost hides behind the MMA stream. 3 bf16 passes
// (xh*wh + xh*wl + xl*wh) accumulated in fp32.
// ======================================================================
__global__ void __launch_bounds__(256, 1)
gemm_mma_kernel()
{
    extern __shared__ char dyn_smem[];
    const uint32_t base = (smem_u32(dyn_smem) + 1023u) & ~1023u;

    const int tid  = threadIdx.x;
    const int wid  = tid >> 5;
    const int lane = tid & 31;

    const int m0 = blockIdx.x * TM;
    const int n0 = blockIdx.y * TN;
    const int split = blockIdx.z;
    const int kbase = split * KSPLIT;

    const int mwarp = (wid >> 2) * 64;   // 0 or 64
    const int nwarp = (wid & 3) * 64;    // 0,64,128,192

    const int a_row = lane & 15;
    const int a_col = (lane >> 4) * 16;
    const int b_row = (lane & 7) + ((lane >> 4) << 3);
    const int b_col = ((lane >> 3) & 1) * 16;

    float c[4][8][4];
    #pragma unroll
    for (int i = 0; i < 4; i++)
        #pragma unroll
        for (int j = 0; j < 8; j++)
            #pragma unroll
            for (int e = 0; e < 4; e++) c[i][j][e] = 0.0f;

    const uint32_t BUFSZ = 98304u;   // 96 KB

    auto issue_loads = [&](int ch) {
        const int k0 = kbase + ch * CK;
        const uint32_t buf = base + ((ch & 1) ? BUFSZ : 0u);
        const __nv_bfloat16* axh = &g_xh[m0][k0];
        const __nv_bfloat16* axl = &g_xl[m0][k0];
        #pragma unroll
        for (int t = 0; t < 4; t++) {
            int q = tid + t * 256;
            int row = q >> 3, qc = q & 7;
            uint32_t off = SWZ128(row * 128 + qc * 16);
            cp_async16(buf +            off, axh + (size_t)row * KPAD + qc * 8);
            cp_async16(buf + 16384u +   off, axl + (size_t)row * KPAD + qc * 8);
        }
        const __nv_bfloat16* bwh = &g_wh[n0][k0];
        const __nv_bfloat16* bwl = &g_wl[n0][k0];
        #pragma unroll
        for (int t = 0; t < 8; t++) {
            int q = tid + t * 256;
            int row = q >> 3, qc = q & 7;
            uint32_t off = SWZ128(row * 128 + qc * 16);
            cp_async16(buf + 32768u + off, bwh + (size_t)row * KPAD + qc * 8);
            cp_async16(buf + 65536u + off, bwl + (size_t)row * KPAD + qc * 8);
        }
        CP_COMMIT();
    };

    issue_loads(0);

    for (int i = 0; i < NCHUNK; i++) {
        CP_WAIT0();          // this thread's copies for chunk i complete
        __syncthreads();     // all threads' copies visible; compute(i-1)
                             // finished by all warps (WAR for buf reuse)

        const uint32_t buf = base + ((i & 1) ? BUFSZ : 0u);
        const uint32_t Ah = buf, Al = buf + 16384u;
        const uint32_t Bh = buf + 32768u, Bl = buf + 65536u;

        #pragma unroll
        for (int kk = 0; kk < 4; kk++) {
            uint32_t ah[4][4], al[4][4];
            #pragma unroll
            for (int t = 0; t < 4; t++) {
                uint32_t offA = SWZ128((mwarp + t * 16 + a_row) * 128 + kk * 32 + a_col);
                LDM_X4(ah[t][0], ah[t][1], ah[t][2], ah[t][3], Ah + offA);
                LDM_X4(al[t][0], al[t][1], al[t][2], al[t][3], Al + offA);
            }
            #pragma unroll
            for (int half = 0; half < 2; half++) {
                uint32_t bh[4][2], bl[4][2];
                #pragma unroll
                for (int t = 0; t < 2; t++) {
                    uint32_t offB = SWZ128((nwarp + half * 32 + t * 16 + b_row) * 128
                                           + kk * 32 + b_col);
                    LDM_X4(bh[2*t][0], bh[2*t][1], bh[2*t+1][0], bh[2*t+1][1], Bh + offB);
                    LDM_X4(bl[2*t][0], bl[2*t][1], bl[2*t+1][0], bl[2*t+1][1], Bl + offB);
                }
                #pragma unroll
                for (int mi = 0; mi < 4; mi++)
                    #pragma unroll
                    for (int nj = 0; nj < 4; nj++) {
                        float* acc = c[mi][half * 4 + nj];
                        mma_bf16(acc, ah[mi], bh[nj]);   // xh * wh
                        mma_bf16(acc, ah[mi], bl[nj]);   // xh * wl
                        mma_bf16(acc, al[mi], bh[nj]);   // xl * wh
                    }
            }
            // issue next chunk's loads after first kk: LSU issue cost
            // hides behind the remaining 3/4 of the MMA stream.
            if (kk == 0 && i + 1 < NCHUNK) issue_loads(i + 1);
        }
    }

    // epilogue: m16n8 frag -> rows (lane/4, +8), cols 2*(lane%4)
    const int er = lane >> 2;
    const int ec = (lane & 3) * 2;
    #pragma unroll
    for (int mi = 0; mi < 4; mi++) {
        const int row = m0 + mwarp + mi * 16 + er;
        #pragma unroll
        for (int nj = 0; nj < 8; nj++) {
            const int col = n0 + nwarp + nj * 8 + ec;
            *reinterpret_cast<float2*>(&g_hpart[split][row][col]) =
                make_float2(c[mi][nj][0], c[mi][nj][1]);
            *reinterpret_cast<float2*>(&g_hpart[split][row + 8][col]) =
                make_float2(c[mi][nj][2], c[mi][nj][3]);
        }
    }
}

// ======================================================================
// Stage 2 (verified 26us shape): one CTA per batch row.
// Reduce split-K partials, +b1, ReLU, then h @ W2 + b2.
// ======================================================================
__global__ void __launch_bounds__(256)
mlp2_kernel(const float* __restrict__ b1,
            const float* __restrict__ W2,
            const float* __restrict__ b2,
            float* __restrict__ out)
{
    __shared__ float hs[NHID];
    const int b   = blockIdx.x;
    const int tid = threadIdx.x;

    #pragma unroll
    for (int n = tid; n < NHID; n += 256) {
        float s = 0.0f;
        #pragma unroll
        for (int sp = 0; sp < SPLITK; sp++) s += g_hpart[sp][b][n];
        s += b1[n];
        hs[n] = fmaxf(s, 0.0f);
    }
    __syncthreads();

    if (tid < NOUT) {
        float a0 = 0.f, a1 = 0.f, a2 = 0.f, a3 = 0.f;
        #pragma unroll 8
        for (int n = 0; n < NHID; n += 4) {
            a0 = fmaf(hs[n + 0], W2[(n + 0) * NOUT + tid], a0);
            a1 = fmaf(hs[n + 1], W2[(n + 1) * NOUT + tid], a1);
            a2 = fmaf(hs[n + 2], W2[(n + 2) * NOUT + tid], a2);
            a3 = fmaf(hs[n + 3], W2[(n + 3) * NOUT + tid], a3);
        }
        out[b * NOUT + tid] = (a0 + a1) + (a2 + a3) + b2[tid];
    }
}

// ======================================================================
// kernel_launch — graph-capturable, allocation-free.
// Input order (metadata): st, at, st1, W1, b1, W2, b2. Output: float32.
// ======================================================================
extern "C" void kernel_launch(void* const* d_in, const int* in_sizes, int n_in,
                              void* d_out, int out_size)
{
    const float* st  = (const float*)d_in[0];
    const float* at  = (const float*)d_in[1];
    const float* st1 = (const float*)d_in[2];
    const float* W1  = (const float*)d_in[3];
    const float* b1  = (const float*)d_in[4];
    const float* W2  = (const float*)d_in[5];
    const float* b2  = (const float*)d_in[6];
    float* out = (float*)d_out;

    convert_all_kernel<<<XBLOCKS + WBLOCKS, 256>>>(st, at, st1, W1);

    const int dyn_smem = 2 * 98304 + 1024;   // 192 KB + align slack
    cudaFuncSetAttribute(gemm_mma_kernel,
                         cudaFuncAttributeMaxDynamicSharedMemorySize, dyn_smem);
    dim3 gg(MT, NT, SPLITK);                 // 8 x 2 x 9 = 144 CTAs, one wave
    gemm_mma_kernel<<<gg, 256, dyn_smem>>>();

    mlp2_kernel<<<NBATCH, 256>>>(b1, W2, b2, out);
}